// round 15
// baseline (speedup 1.0000x reference)
#include <cuda_runtime.h>
#include <cstdint>

#define DEV_INLINE __device__ __forceinline__

constexpr int cN   = 100000;   // nodes
constexpr int cE   = 1600000;  // edges
constexpr int cDIN = 32;       // node in channels
constexpr int cDE  = 16;       // edge feature dim
constexpr int cH   = 64;       // hidden
constexpr int cMH  = 128;      // mlp hidden
constexpr int cOUT = 10;       // out channels
constexpr int cG   = 128;      // graphs
constexpr int EPW  = 64;       // edges per warp (2 pipelined chunks of 32)

typedef unsigned long long ull;

// ---------------- scratch (device globals; no allocation allowed) ----------
__device__ __align__(16) float g_u[cN * cH];       // x + agg (node MLP input)
__device__ __align__(16) float g_h[cN * cH];       // node MLP output (pre-BN)
__device__ __align__(16) float g_x[cN * cH];       // post-BN activations
__device__ __align__(16) float g_ea_perm[(size_t)cE * cDE];  // ea in CSR order
__device__ __align__(16) float g_proj[(size_t)3 * cE * cH];  // per-layer edge proj
__device__ __align__(16) int   g_src[cE];          // src in CSR order
__device__ __align__(16) int   g_dst[cE];          // dst in CSR order (sorted)
__device__ __align__(16) int   g_deg[cN];          // zeroed by scan (self-restoring)
__device__ __align__(16) int   g_woff[cN];
__device__ __align__(16) int   g_rowptr[cN + 1];
__device__ __align__(16) float g_sum[cH];
__device__ __align__(16) float g_sumsq[cH];
__device__ __align__(16) float g_pool[cG * cH];
__device__ __align__(16) int   g_cnt[cG];

DEV_INLINE void red_add_v4(float* p, float a, float b, float c, float d) {
    asm volatile("red.global.add.v4.f32 [%0], {%1,%2,%3,%4};"
                 :: "l"(p), "f"(a), "f"(b), "f"(c), "f"(d) : "memory");
}
DEV_INLINE void red_add_v2(float* p, float a, float b) {
    asm volatile("red.global.add.v2.f32 [%0], {%1,%2};"
                 :: "l"(p), "f"(a), "f"(b) : "memory");
}
DEV_INLINE void red_add_1(float* p, float a) {
    asm volatile("red.global.add.f32 [%0], %1;" :: "l"(p), "f"(a) : "memory");
}
DEV_INLINE ull ffma2(ull a, ull b, ull c) {
    ull d;
    asm("fma.rn.f32x2 %0, %1, %2, %3;" : "=l"(d) : "l"(a), "l"(b), "l"(c));
    return d;
}
DEV_INLINE ull pack2(float lo, float hi) {
    ull v;
    asm("mov.b64 %0, {%1, %2};" : "=l"(v) : "f"(lo), "f"(hi));
    return v;
}
DEV_INLINE float2 unpack2(ull v) {
    float2 f;
    asm("mov.b64 {%0, %1}, %2;" : "=f"(f.x), "=f"(f.y) : "l"(v));
    return f;
}
DEV_INLINE uint32_t s2u(const void* p) {
    uint32_t a;
    asm("{ .reg .u64 t; cvta.to.shared.u64 t, %1; cvt.u32.u64 %0, t; }"
        : "=r"(a) : "l"(p));
    return a;
}
DEV_INLINE void cp16(uint32_t smem, const void* g) {
    asm volatile("cp.async.ca.shared.global [%0], [%1], 16;"
                 :: "r"(smem), "l"(g) : "memory");
}
#define CP_COMMIT() asm volatile("cp.async.commit_group;" ::: "memory")
#define CP_WAIT1()  asm volatile("cp.async.wait_group 1;" ::: "memory")
#define CP_WAIT0()  asm volatile("cp.async.wait_group 0;" ::: "memory")

// ---------------- CSR build -------------------------------------------------
// hist also zeroes pool/cnt and seeds g_u = x (layer-0 input).
// g_deg is zero at load and re-zeroed by scan each call: deterministic.
__global__ void __launch_bounds__(256) hist_kernel(
    const int* __restrict__ ei, const float* __restrict__ x)
{
    int i = blockIdx.x * 256 + threadIdx.x;
    if (i < cG * cH) g_pool[i] = 0.f;
    if (i < cG) g_cnt[i] = 0;
    if (i < cN * cDIN / 4) ((float4*)g_u)[i] = ((const float4*)x)[i];
    if (i < cE) atomicAdd(&g_deg[ei[cE + i]], 1);
}

__global__ void __launch_bounds__(1024) scan_kernel() {
    const int TP = (cN + 1023) / 1024;  // 98
    int t = threadIdx.x;
    int s0 = t * TP, s1 = min(s0 + TP, cN);
    int ls = 0;
    for (int i = s0; i < s1; i++) ls += g_deg[i];
    __shared__ int ps[1024];
    ps[t] = ls;
    __syncthreads();
    for (int off = 1; off < 1024; off <<= 1) {
        int v = (t >= off) ? ps[t - off] : 0;
        __syncthreads();
        ps[t] += v;
        __syncthreads();
    }
    int run = ps[t] - ls;
    for (int i = s0; i < s1; i++) {
        int d = g_deg[i];
        g_deg[i] = 0;          // restore for next call's hist
        g_rowptr[i] = run;
        g_woff[i]   = run;
        run += d;
    }
    if (t == 0) g_rowptr[cN] = cE;
}

// scatter + permute edge_attr into CSR (dst-sorted) order, fused
__global__ void __launch_bounds__(256) scatter_kernel(
    const int* __restrict__ ei, const float* __restrict__ ea)
{
    int e = blockIdx.x * 256 + threadIdx.x;
    if (e >= cE) return;
    int s = ei[e], d = ei[cE + e];
    int pos = atomicAdd(&g_woff[d], 1);
    g_src[pos] = s;
    g_dst[pos] = d;
    const float4* sp = (const float4*)(ea + (size_t)e * cDE);
    float4 a = sp[0], b = sp[1], c = sp[2], dd = sp[3];
    float4* dp = (float4*)(g_ea_perm + (size_t)pos * cDE);
    dp[0] = a; dp[1] = b; dp[2] = c; dp[3] = dd;
}

// ---------------- edge projection (streaming GEMM, CSR order) --------------
// g_proj[layer][e][c] = ea_perm[e] @ ew^T + eb.  Depends only on edge_attr
// and weights -> runs right after scatter for all 3 H-layers.
__global__ void __launch_bounds__(256) proj_kernel(
    const float* __restrict__ ew, const float* __restrict__ eb, int layer)
{
    constexpr int KP = cDE / 2;  // 8 k-pairs

    __shared__ __align__(16) float ea_s[8][2][32 * cDE];   // 32KB

    float* po = g_proj + (size_t)layer * cE * cH;
    int t = threadIdx.x;
    int lane = t & 31;
    int w = t >> 5;
    int c0 = lane * 2;

    ull wreg[2][KP];
    float ebr[2];
    #pragma unroll
    for (int c = 0; c < 2; c++) {
        #pragma unroll
        for (int j = 0; j < KP; j++)
            wreg[c][j] = *(const ull*)&ew[(c0 + c) * cDE + 2 * j];
        ebr[c] = eb[c0 + c];
    }

    int base = (blockIdx.x * 8 + w) * EPW;

    uint32_t sb0 = s2u(&ea_s[w][0][0]);
    uint32_t sb1 = s2u(&ea_s[w][1][0]);
    const char* gp = (const char*)(g_ea_perm) + (size_t)base * (cDE * 4);
    #pragma unroll
    for (int i = 0; i < 4; i++)
        cp16(sb0 + i * 512 + lane * 16, gp + i * 512 + lane * 16);
    CP_COMMIT();
    #pragma unroll
    for (int i = 0; i < 4; i++)
        cp16(sb1 + i * 512 + lane * 16, gp + 2048 + i * 512 + lane * 16);
    CP_COMMIT();

    auto run = [&](const float* eabuf, int eb0) {
        #pragma unroll 4
        for (int g = 0; g < 32; g++) {
            const ulonglong2* eap = (const ulonglong2*)(eabuf + g * cDE);
            ulonglong2 p0 = eap[0], p1 = eap[1], p2 = eap[2], p3 = eap[3];
            ull d0 = pack2(ebr[0], 0.f), d1 = pack2(ebr[1], 0.f);
            d0 = ffma2(wreg[0][0], p0.x, d0); d1 = ffma2(wreg[1][0], p0.x, d1);
            d0 = ffma2(wreg[0][1], p0.y, d0); d1 = ffma2(wreg[1][1], p0.y, d1);
            d0 = ffma2(wreg[0][2], p1.x, d0); d1 = ffma2(wreg[1][2], p1.x, d1);
            d0 = ffma2(wreg[0][3], p1.y, d0); d1 = ffma2(wreg[1][3], p1.y, d1);
            d0 = ffma2(wreg[0][4], p2.x, d0); d1 = ffma2(wreg[1][4], p2.x, d1);
            d0 = ffma2(wreg[0][5], p2.y, d0); d1 = ffma2(wreg[1][5], p2.y, d1);
            d0 = ffma2(wreg[0][6], p3.x, d0); d1 = ffma2(wreg[1][6], p3.x, d1);
            d0 = ffma2(wreg[0][7], p3.y, d0); d1 = ffma2(wreg[1][7], p3.y, d1);
            float2 pa = unpack2(d0), pb = unpack2(d1);
            *(float2*)(po + (size_t)(eb0 + g) * cH + c0) =
                make_float2(pa.x + pa.y, pb.x + pb.y);
        }
    };

    CP_WAIT1();
    __syncwarp();
    run(&ea_s[w][0][0], base);
    CP_WAIT0();
    __syncwarp();
    run(&ea_s[w][1][0], base + 32);
}

// ---------------- light gather: g_u[d] += relu(g_x[src] + proj[e]) ---------
// Warp owns 64 CSR edges (2 chunks of 32). No smem, no weights; segment
// boundaries via ballot; flush per chunk (always safe: atomic partials).
__global__ void __launch_bounds__(256) gatherlite_kernel(int layer)
{
    const float* pj = g_proj + (size_t)layer * cE * cH;
    int t = threadIdx.x;
    int lane = t & 31;
    int w = t >> 5;

    if (blockIdx.x == 0 && t < cH) { g_sum[t] = 0.f; g_sumsq[t] = 0.f; }

    int c0 = lane * 2;
    int base = (blockIdx.x * 8 + w) * EPW;

    int sc0 = g_src[base + lane],  sc1 = g_src[base + 32 + lane];
    int dc0 = g_dst[base + lane],  dc1 = g_dst[base + 32 + lane];

    auto chunk = [&](int sc, int dc, int e0) {
        int prev = __shfl_up_sync(0xffffffffu, dc, 1);
        unsigned mask = __ballot_sync(0xffffffffu, lane > 0 && dc != prev);
        int cur = __shfl_sync(0xffffffffu, dc, 0);
        float acc0 = 0.f, acc1 = 0.f;
        for (int g = 0; g < 32; g += 4) {
            int ss[4];
            #pragma unroll
            for (int r = 0; r < 4; r++) ss[r] = __shfl_sync(0xffffffffu, sc, g + r);
            float2 xv[4], pv[4];
            #pragma unroll
            for (int r = 0; r < 4; r++)
                xv[r] = *(const float2*)(g_x + (size_t)ss[r] * cH + c0);
            #pragma unroll
            for (int r = 0; r < 4; r++)
                pv[r] = *(const float2*)(pj + (size_t)(e0 + g + r) * cH + c0);
            #pragma unroll
            for (int r = 0; r < 4; r++) {
                if ((mask >> (g + r)) & 1u) {   // warp-uniform
                    red_add_v2(&g_u[(size_t)cur * cH + c0], acc0, acc1);
                    acc0 = 0.f; acc1 = 0.f;
                    cur = __shfl_sync(0xffffffffu, dc, g + r);
                }
                acc0 += fmaxf(xv[r].x + pv[r].x, 0.f);
                acc1 += fmaxf(xv[r].y + pv[r].y, 0.f);
            }
        }
        red_add_v2(&g_u[(size_t)cur * cH + c0], acc0, acc1);
    };

    chunk(sc0, dc0, base);
    chunk(sc1, dc1, base + 32);
}

// ---------------- layer-0 unified gather (C=32) ----------------------------
__global__ void __launch_bounds__(256) gather0_kernel(
    const float* __restrict__ x,
    const float* __restrict__ ew, const float* __restrict__ eb)
{
    constexpr int C  = cDIN;
    constexpr int KP = cDE / 2;

    __shared__ __align__(16) float ea_s[8][2][32 * cDE];   // 32KB

    int t = threadIdx.x;
    int lane = t & 31;
    int w = t >> 5;

    if (blockIdx.x == 0 && t < cH) { g_sum[t] = 0.f; g_sumsq[t] = 0.f; }

    int c0 = lane;
    ull wreg[KP];
    float ebr;
    #pragma unroll
    for (int j = 0; j < KP; j++)
        wreg[j] = *(const ull*)&ew[c0 * cDE + 2 * j];
    ebr = eb[c0];

    int base = (blockIdx.x * 8 + w) * EPW;

    int sc0 = g_src[base + lane],  sc1 = g_src[base + 32 + lane];
    int dc0 = g_dst[base + lane],  dc1 = g_dst[base + 32 + lane];

    uint32_t sb0 = s2u(&ea_s[w][0][0]);
    uint32_t sb1 = s2u(&ea_s[w][1][0]);
    const char* gp = (const char*)(g_ea_perm) + (size_t)base * (cDE * 4);
    #pragma unroll
    for (int i = 0; i < 4; i++)
        cp16(sb0 + i * 512 + lane * 16, gp + i * 512 + lane * 16);
    CP_COMMIT();
    #pragma unroll
    for (int i = 0; i < 4; i++)
        cp16(sb1 + i * 512 + lane * 16, gp + 2048 + i * 512 + lane * 16);
    CP_COMMIT();

    float acc0 = 0.f;
    int cur = __shfl_sync(0xffffffffu, dc0, 0);

    auto process = [&](const float* eabuf, int sc, int dc) {
        for (int g = 0; g < 32; g += 4) {
            int ss[4], dd[4];
            #pragma unroll
            for (int r = 0; r < 4; r++) {
                ss[r] = __shfl_sync(0xffffffffu, sc, g + r);
                dd[r] = __shfl_sync(0xffffffffu, dc, g + r);
            }
            float xa[4];
            #pragma unroll
            for (int r = 0; r < 4; r++) xa[r] = x[(size_t)ss[r] * C + c0];
            #pragma unroll
            for (int r = 0; r < 4; r++) {
                if (dd[r] != cur) {   // warp-uniform
                    red_add_1(&g_u[(size_t)cur * C + c0], acc0);
                    acc0 = 0.f;
                    cur = dd[r];
                }
                const ulonglong2* eap = (const ulonglong2*)(eabuf + (g + r) * cDE);
                ulonglong2 p0 = eap[0], p1 = eap[1], p2 = eap[2], p3 = eap[3];
                ull d0 = pack2(ebr, 0.f);
                d0 = ffma2(wreg[0], p0.x, d0);
                d0 = ffma2(wreg[1], p0.y, d0);
                d0 = ffma2(wreg[2], p1.x, d0);
                d0 = ffma2(wreg[3], p1.y, d0);
                d0 = ffma2(wreg[4], p2.x, d0);
                d0 = ffma2(wreg[5], p2.y, d0);
                d0 = ffma2(wreg[6], p3.x, d0);
                d0 = ffma2(wreg[7], p3.y, d0);
                float2 pa = unpack2(d0);
                acc0 += fmaxf(xa[r] + pa.x + pa.y, 0.f);
            }
        }
    };

    CP_WAIT1();
    __syncwarp();
    process(&ea_s[w][0][0], sc0, dc0);
    CP_WAIT0();
    __syncwarp();
    process(&ea_s[w][1][0], sc1, dc1);

    red_add_1(&g_u[(size_t)cur * C + c0], acc0);
}

// ---------------- node update: h2 = relu(relu(u W1^T + b1) W2^T + b2) ------
template <int CIN>
__global__ void __launch_bounds__(256, 2) node_kernel(
    const float* __restrict__ w1, const float* __restrict__ b1,
    const float* __restrict__ w2, const float* __restrict__ b2)
{
    constexpr int KP1 = CIN / 2;   // 16 or 32
    constexpr int US  = KP1 + 1;
    constexpr int KP2 = cH / 2;    // 32
    constexpr int HS  = KP2 + 1;   // 33
    constexpr int WS  = KP2 + 1;

    extern __shared__ __align__(16) ull dyn[];
    ull* us2 = dyn;                    // [128 * US]
    ull* ws2 = us2 + 128 * US;         // [64 * WS]
    ull* hs2 = ws2 + 64 * WS;          // [128 * HS]
    float* hsf = (float*)hs2;

    int t = threadIdx.x;
    int lane = t & 31;
    int w = t >> 5;
    int n0 = blockIdx.x * 128;

    for (int i = t; i < 128 * KP1; i += 256) {
        int n = i / KP1, j = i % KP1;
        us2[n * US + j] = (n0 + n < cN)
            ? *(const ull*)&g_u[(size_t)(n0 + n) * CIN + 2 * j] : 0ull;
    }
    for (int i = t; i < cH * KP1; i += 256) {
        int r = i / KP1, j = i % KP1;
        ws2[r * WS + j] = ((const ull*)w1)[i];
    }
    __syncthreads();

    // ---- GEMM 1 ----
    ull acc2[4][8];
    #pragma unroll
    for (int j = 0; j < 8; j++) {
        ull b = pack2(b1[w * 8 + j], 0.f);
        #pragma unroll
        for (int i = 0; i < 4; i++) acc2[i][j] = b;
    }
    for (int kp = 0; kp < KP1; kp++) {
        ull wt[8], uv[4];
        #pragma unroll
        for (int j = 0; j < 8; j++) wt[j] = ws2[(w * 8 + j) * WS + kp];
        #pragma unroll
        for (int i = 0; i < 4; i++) uv[i] = us2[(lane + 32 * i) * US + kp];
        #pragma unroll
        for (int i = 0; i < 4; i++)
            #pragma unroll
            for (int j = 0; j < 8; j++)
                acc2[i][j] = ffma2(wt[j], uv[i], acc2[i][j]);
    }
    #pragma unroll
    for (int i = 0; i < 4; i++) {
        int n = lane + 32 * i;
        #pragma unroll
        for (int j = 0; j < 8; j += 2) {
            float2 pa = unpack2(acc2[i][j]);
            float2 pb = unpack2(acc2[i][j + 1]);
            ull pk = pack2(fmaxf(pa.x + pa.y, 0.f), fmaxf(pb.x + pb.y, 0.f));
            *(ull*)&hsf[n * (2 * HS) + w * 8 + j] = pk;
        }
    }
    __syncthreads();

    for (int i = t; i < cH * KP2; i += 256) {
        int r = i / KP2, j = i % KP2;
        ws2[r * WS + j] = ((const ull*)w2)[i];
    }
    __syncthreads();

    // ---- GEMM 2 ----
    #pragma unroll
    for (int j = 0; j < 8; j++) {
        ull b = pack2(b2[w * 8 + j], 0.f);
        #pragma unroll
        for (int i = 0; i < 4; i++) acc2[i][j] = b;
    }
    for (int kp = 0; kp < KP2; kp++) {
        ull wt[8], uv[4];
        #pragma unroll
        for (int j = 0; j < 8; j++) wt[j] = ws2[(w * 8 + j) * WS + kp];
        #pragma unroll
        for (int i = 0; i < 4; i++) uv[i] = hs2[(lane + 32 * i) * HS + kp];
        #pragma unroll
        for (int i = 0; i < 4; i++)
            #pragma unroll
            for (int j = 0; j < 8; j++)
                acc2[i][j] = ffma2(wt[j], uv[i], acc2[i][j]);
    }

    float v[4][8];
    float s[8], q[8];
    #pragma unroll
    for (int j = 0; j < 8; j++) { s[j] = 0.f; q[j] = 0.f; }
    #pragma unroll
    for (int i = 0; i < 4; i++) {
        bool valid = (n0 + lane + 32 * i) < cN;
        #pragma unroll
        for (int j = 0; j < 8; j++) {
            float2 p = unpack2(acc2[i][j]);
            float vv = valid ? fmaxf(p.x + p.y, 0.f) : 0.f;
            v[i][j] = vv;
            s[j] += vv; q[j] += vv * vv;
        }
    }
    #pragma unroll
    for (int j = 0; j < 8; j++) {
        #pragma unroll
        for (int off = 16; off > 0; off >>= 1) {
            s[j] += __shfl_xor_sync(0xffffffffu, s[j], off);
            q[j] += __shfl_xor_sync(0xffffffffu, q[j], off);
        }
    }
    if (lane == 0) {
        #pragma unroll
        for (int j = 0; j < 8; j++) {
            atomicAdd(&g_sum[w * 8 + j], s[j]);
            atomicAdd(&g_sumsq[w * 8 + j], q[j]);
        }
    }

    __syncthreads();
    #pragma unroll
    for (int i = 0; i < 4; i++) {
        int n = lane + 32 * i;
        #pragma unroll
        for (int j = 0; j < 8; j += 2) {
            ull pk = pack2(v[i][j], v[i][j + 1]);
            *(ull*)&hsf[n * (2 * HS) + w * 8 + j] = pk;
        }
    }
    __syncthreads();
    for (int i = t; i < 128 * cH / 2; i += 256) {
        int n = i / KP2, j = i % KP2;
        if (n0 + n < cN)
            *(ull*)&g_h[(size_t)(n0 + n) * cH + 2 * j] = *(ull*)&hsf[n * (2 * HS) + 2 * j];
    }
}

// ---------------- BN normalize (+relu); writes g_x and (if !last) g_u ------
__global__ void __launch_bounds__(256) norm_kernel(
    const float* __restrict__ gamma, const float* __restrict__ beta,
    const int* __restrict__ batch, int last)
{
    int idx = blockIdx.x * 256 + threadIdx.x;
    if (idx >= cN * 16) return;
    int node = idx >> 4;
    int c0 = (idx & 15) * 4;
    float4 h = ((const float4*)g_h)[idx];
    float v[4] = {h.x, h.y, h.z, h.w};
    #pragma unroll
    for (int j = 0; j < 4; j++) {
        int c = c0 + j;
        float mu  = g_sum[c]   * (1.f / cN);
        float var = g_sumsq[c] * (1.f / cN) - mu * mu;
        float sc  = rsqrtf(var + 1e-5f) * gamma[c];
        v[j] = fmaxf((v[j] - mu) * sc + beta[c], 0.f);
    }
    float4 vv = make_float4(v[0], v[1], v[2], v[3]);
    ((float4*)g_x)[idx] = vv;
    if (!last) {
        ((float4*)g_u)[idx] = vv;     // seed u = x for next layer's gather
    } else {
        int b = batch[node];
        red_add_v4(&g_pool[b * cH + c0], v[0], v[1], v[2], v[3]);
        if (c0 == 0) atomicAdd(&g_cnt[b], 1);
    }
}

// ---------------- pooled mean + MLP head -----------------------------------
__global__ void __launch_bounds__(128) head_kernel(
    const float* __restrict__ hw1, const float* __restrict__ hb1,
    const float* __restrict__ hw2, const float* __restrict__ hb2,
    float* __restrict__ out)
{
    __shared__ float p[cH], z[cMH];
    int g = blockIdx.x, t = threadIdx.x;
    if (t < cH) p[t] = g_pool[g * cH + t] / fmaxf((float)g_cnt[g], 1.f);
    __syncthreads();
    float acc = hb1[t];
    for (int c = 0; c < cH; c++) acc += p[c] * hw1[t * cH + c];
    z[t] = fmaxf(acc, 0.f);
    __syncthreads();
    if (t < cOUT) {
        float a = hb2[t];
        for (int m = 0; m < cMH; m++) a += z[m] * hw2[t * cMH + m];
        out[g * cOUT + t] = a;
    }
}

// ---------------- launch ----------------------------------------------------
extern "C" void kernel_launch(void* const* d_in, const int* in_sizes, int n_in,
                              void* d_out, int out_size)
{
    const float* x    = (const float*)d_in[0];
    const int*   ei   = (const int*)  d_in[1];
    const float* ea   = (const float*)d_in[2];
    const int*   batch= (const int*)  d_in[3];
    const float* l0ew = (const float*)d_in[4];
    const float* l0eb = (const float*)d_in[5];
    const float* l0w1 = (const float*)d_in[6];
    const float* l0b1 = (const float*)d_in[7];
    const float* l0w2 = (const float*)d_in[8];
    const float* l0b2 = (const float*)d_in[9];
    const float* ewA  = (const float*)d_in[10];  // [3, H, DE]
    const float* ebA  = (const float*)d_in[11];  // [3, H]
    const float* w1A  = (const float*)d_in[12];  // [3, H, H]
    const float* b1A  = (const float*)d_in[13];
    const float* w2A  = (const float*)d_in[14];
    const float* b2A  = (const float*)d_in[15];
    const float* bng  = (const float*)d_in[16];  // [4, H]
    const float* bnb  = (const float*)d_in[17];
    const float* hw1  = (const float*)d_in[18];
    const float* hb1  = (const float*)d_in[19];
    const float* hw2  = (const float*)d_in[20];
    const float* hb2  = (const float*)d_in[21];
    float* out = (float*)d_out;

    const int EB = (cE + 255) / 256;       // 6250
    const int GB = cE / (8 * EPW);         // 3125 (exact: 1.6M / 512)
    const int NB = (cN + 127) / 128;       // 782
    const int MB = cN * 16 / 256;          // 6250

    const int SM32 = (128 * (cDIN / 2 + 1) + cH * 33 + 128 * 33) * 8;
    const int SM64 = (128 * (cH   / 2 + 1) + cH * 33 + 128 * 33) * 8;
    cudaFuncSetAttribute(node_kernel<cDIN>,
                         cudaFuncAttributeMaxDynamicSharedMemorySize, SM32);
    cudaFuncSetAttribute(node_kernel<cH>,
                         cudaFuncAttributeMaxDynamicSharedMemorySize, SM64);

    // CSR build (by dst) + edge_attr permutation + g_u seed
    hist_kernel<<<EB, 256>>>(ei, x);
    scan_kernel<<<1, 1024>>>();
    scatter_kernel<<<EB, 256>>>(ei, ea);

    // edge projections for layers 1..3 (independent of node features);
    // proj_kernel is the 4th launch -> ncu capture target
    for (int i = 0; i < 3; i++)
        proj_kernel<<<GB, 256>>>(ewA + (size_t)i * cH * cDE,
                                 ebA + (size_t)i * cH, i);

    // layer 0 (CIN = 32), unified gather
    gather0_kernel<<<GB, 256>>>(x, l0ew, l0eb);
    node_kernel<cDIN><<<NB, 256, SM32>>>(l0w1, l0b1, l0w2, l0b2);
    norm_kernel<<<MB, 256>>>(bng, bnb, batch, 0);

    // layers 1..3 (CIN = 64): light gather using precomputed proj
    for (int i = 0; i < 3; i++) {
        int last = (i == 2) ? 1 : 0;
        gatherlite_kernel<<<GB, 256>>>(i);
        node_kernel<cH><<<NB, 256, SM64>>>(w1A + (size_t)i * cH * cH, b1A + (size_t)i * cH,
                                           w2A + (size_t)i * cH * cH, b2A + (size_t)i * cH);
        norm_kernel<<<MB, 256>>>(bng + (size_t)(i + 1) * cH,
                                 bnb + (size_t)(i + 1) * cH, batch, last);
    }

    head_kernel<<<cG, 128>>>(hw1, hb1, hw2, hb2, out);
}

// round 16
// speedup vs baseline: 1.1432x; 1.1432x over previous
#include <cuda_runtime.h>
#include <cstdint>

#define DEV_INLINE __device__ __forceinline__

constexpr int cN   = 100000;   // nodes
constexpr int cE   = 1600000;  // edges
constexpr int cDIN = 32;       // node in channels
constexpr int cDE  = 16;       // edge feature dim
constexpr int cH   = 64;       // hidden
constexpr int cMH  = 128;      // mlp hidden
constexpr int cOUT = 10;       // out channels
constexpr int cG   = 128;      // graphs
constexpr int EPW  = 64;       // edges per warp(-pair): 2 pipelined chunks of 32

typedef unsigned long long ull;

// ---------------- scratch (device globals; no allocation allowed) ----------
__device__ __align__(16) float g_u[cN * cH];       // x + agg (node MLP input)
__device__ __align__(16) float g_h[cN * cH];       // node MLP output (pre-BN)
__device__ __align__(16) float g_x[cN * cH];       // post-BN activations
__device__ __align__(16) float g_ea_perm[(size_t)cE * cDE];  // ea in CSR order
__device__ __align__(16) int   g_src[cE];          // src in CSR order
__device__ __align__(16) int   g_dst[cE];          // dst in CSR order (sorted)
__device__ __align__(16) int   g_deg[cN];          // zeroed by scan (self-restoring)
__device__ __align__(16) int   g_woff[cN];
__device__ __align__(16) int   g_rowptr[cN + 1];
__device__ __align__(16) float g_sum[cH];
__device__ __align__(16) float g_sumsq[cH];
__device__ __align__(16) float g_pool[cG * cH];
__device__ __align__(16) int   g_cnt[cG];

DEV_INLINE void red_add_v4(float* p, float a, float b, float c, float d) {
    asm volatile("red.global.add.v4.f32 [%0], {%1,%2,%3,%4};"
                 :: "l"(p), "f"(a), "f"(b), "f"(c), "f"(d) : "memory");
}
DEV_INLINE void red_add_1(float* p, float a) {
    asm volatile("red.global.add.f32 [%0], %1;" :: "l"(p), "f"(a) : "memory");
}
DEV_INLINE ull ffma2(ull a, ull b, ull c) {
    ull d;
    asm("fma.rn.f32x2 %0, %1, %2, %3;" : "=l"(d) : "l"(a), "l"(b), "l"(c));
    return d;
}
DEV_INLINE ull pack2(float lo, float hi) {
    ull v;
    asm("mov.b64 %0, {%1, %2};" : "=l"(v) : "f"(lo), "f"(hi));
    return v;
}
DEV_INLINE float2 unpack2(ull v) {
    float2 f;
    asm("mov.b64 {%0, %1}, %2;" : "=f"(f.x), "=f"(f.y) : "l"(v));
    return f;
}
DEV_INLINE uint32_t s2u(const void* p) {
    uint32_t a;
    asm("{ .reg .u64 t; cvta.to.shared.u64 t, %1; cvt.u32.u64 %0, t; }"
        : "=r"(a) : "l"(p));
    return a;
}
DEV_INLINE void cp16(uint32_t smem, const void* g) {
    asm volatile("cp.async.ca.shared.global [%0], [%1], 16;"
                 :: "r"(smem), "l"(g) : "memory");
}
#define CP_COMMIT() asm volatile("cp.async.commit_group;" ::: "memory")
#define CP_WAIT1()  asm volatile("cp.async.wait_group 1;" ::: "memory")
#define CP_WAIT0()  asm volatile("cp.async.wait_group 0;" ::: "memory")

// ---------------- CSR build -------------------------------------------------
// hist also zeroes pool/cnt and seeds g_u = x (layer-0 input).
// g_deg is zero at load and re-zeroed by scan each call: deterministic.
__global__ void __launch_bounds__(256) hist_kernel(
    const int* __restrict__ ei, const float* __restrict__ x)
{
    int i = blockIdx.x * 256 + threadIdx.x;
    if (i < cG * cH) g_pool[i] = 0.f;
    if (i < cG) g_cnt[i] = 0;
    if (i < cN * cDIN / 4) ((float4*)g_u)[i] = ((const float4*)x)[i];
    if (i < cE) atomicAdd(&g_deg[ei[cE + i]], 1);
}

__global__ void __launch_bounds__(1024) scan_kernel() {
    const int TP = (cN + 1023) / 1024;  // 98
    int t = threadIdx.x;
    int s0 = t * TP, s1 = min(s0 + TP, cN);
    int ls = 0;
    for (int i = s0; i < s1; i++) ls += g_deg[i];
    __shared__ int ps[1024];
    ps[t] = ls;
    __syncthreads();
    for (int off = 1; off < 1024; off <<= 1) {
        int v = (t >= off) ? ps[t - off] : 0;
        __syncthreads();
        ps[t] += v;
        __syncthreads();
    }
    int run = ps[t] - ls;
    for (int i = s0; i < s1; i++) {
        int d = g_deg[i];
        g_deg[i] = 0;          // restore for next call's hist
        g_rowptr[i] = run;
        g_woff[i]   = run;
        run += d;
    }
    if (t == 0) g_rowptr[cN] = cE;
}

// scatter + permute edge_attr into CSR (dst-sorted) order, fused
__global__ void __launch_bounds__(256) scatter_kernel(
    const int* __restrict__ ei, const float* __restrict__ ea)
{
    int e = blockIdx.x * 256 + threadIdx.x;
    if (e >= cE) return;
    int s = ei[e], d = ei[cE + e];
    int pos = atomicAdd(&g_woff[d], 1);
    g_src[pos] = s;
    g_dst[pos] = d;
    const float4* sp = (const float4*)(ea + (size_t)e * cDE);
    float4 a = sp[0], b = sp[1], c = sp[2], dd = sp[3];
    float4* dp = (float4*)(g_ea_perm + (size_t)pos * cDE);
    dp[0] = a; dp[1] = b; dp[2] = c; dp[3] = dd;
}

// ---------------- layer-0 gather (C=32, warp-per-64-edges) -----------------
__global__ void __launch_bounds__(256) gather0_kernel(
    const float* __restrict__ x,
    const float* __restrict__ ew, const float* __restrict__ eb)
{
    constexpr int C  = cDIN;
    constexpr int KP = cDE / 2;

    __shared__ __align__(16) float ea_s[8][2][32 * cDE];   // 32KB

    int t = threadIdx.x;
    int lane = t & 31;
    int w = t >> 5;

    if (blockIdx.x == 0 && t < cH) { g_sum[t] = 0.f; g_sumsq[t] = 0.f; }

    int c0 = lane;
    ull wreg[KP];
    #pragma unroll
    for (int j = 0; j < KP; j++)
        wreg[j] = *(const ull*)&ew[c0 * cDE + 2 * j];
    float ebr = eb[c0];

    int base = (blockIdx.x * 8 + w) * EPW;

    int sc0 = g_src[base + lane],  sc1 = g_src[base + 32 + lane];
    int dc0 = g_dst[base + lane],  dc1 = g_dst[base + 32 + lane];

    uint32_t sb0 = s2u(&ea_s[w][0][0]);
    uint32_t sb1 = s2u(&ea_s[w][1][0]);
    const char* gp = (const char*)(g_ea_perm) + (size_t)base * (cDE * 4);
    #pragma unroll
    for (int i = 0; i < 4; i++)
        cp16(sb0 + i * 512 + lane * 16, gp + i * 512 + lane * 16);
    CP_COMMIT();
    #pragma unroll
    for (int i = 0; i < 4; i++)
        cp16(sb1 + i * 512 + lane * 16, gp + 2048 + i * 512 + lane * 16);
    CP_COMMIT();

    float acc0 = 0.f;
    int cur = __shfl_sync(0xffffffffu, dc0, 0);

    auto process = [&](const float* eabuf, int sc, int dc) {
        for (int g = 0; g < 32; g += 4) {
            int ss[4], dd[4];
            #pragma unroll
            for (int r = 0; r < 4; r++) {
                ss[r] = __shfl_sync(0xffffffffu, sc, g + r);
                dd[r] = __shfl_sync(0xffffffffu, dc, g + r);
            }
            float xa[4];
            #pragma unroll
            for (int r = 0; r < 4; r++) xa[r] = x[(size_t)ss[r] * C + c0];
            #pragma unroll
            for (int r = 0; r < 4; r++) {
                if (dd[r] != cur) {   // warp-uniform
                    red_add_1(&g_u[(size_t)cur * C + c0], acc0);
                    acc0 = 0.f;
                    cur = dd[r];
                }
                const ulonglong2* eap = (const ulonglong2*)(eabuf + (g + r) * cDE);
                ulonglong2 p0 = eap[0], p1 = eap[1], p2 = eap[2], p3 = eap[3];
                ull d0 = pack2(ebr, 0.f);
                d0 = ffma2(wreg[0], p0.x, d0);
                d0 = ffma2(wreg[1], p0.y, d0);
                d0 = ffma2(wreg[2], p1.x, d0);
                d0 = ffma2(wreg[3], p1.y, d0);
                d0 = ffma2(wreg[4], p2.x, d0);
                d0 = ffma2(wreg[5], p2.y, d0);
                d0 = ffma2(wreg[6], p3.x, d0);
                d0 = ffma2(wreg[7], p3.y, d0);
                float2 pa = unpack2(d0);
                acc0 += fmaxf(xa[r] + pa.x + pa.y, 0.f);
            }
        }
    };

    CP_WAIT1();
    __syncwarp();
    process(&ea_s[w][0][0], sc0, dc0);
    CP_WAIT0();
    __syncwarp();
    process(&ea_s[w][1][0], sc1, dc1);

    red_add_1(&g_u[(size_t)cur * C + c0], acc0);
}

// ---------------- H-layer gather (C=64, warp-PAIR per 64 edges) ------------
// Two warps co-own the same 64-edge CSR range; warp half h handles channels
// [32h, 32h+32), CPT=1 -> low register pressure. Shared cp.async ea staging
// (each warp copies half of each 2KB chunk; block-wide sync after wait).
__global__ void __launch_bounds__(256) gather64_kernel(
    const float* __restrict__ ew, const float* __restrict__ eb)
{
    constexpr int KP = cDE / 2;

    __shared__ __align__(16) float ea_s[4][2][32 * cDE];   // 16KB

    int t = threadIdx.x;
    int lane = t & 31;
    int w = t >> 5;
    int pair = w >> 1, half = w & 1;

    if (blockIdx.x == 0 && t < cH) { g_sum[t] = 0.f; g_sumsq[t] = 0.f; }

    int c0 = half * 32 + lane;
    ull wreg[KP];
    #pragma unroll
    for (int j = 0; j < KP; j++)
        wreg[j] = *(const ull*)&ew[c0 * cDE + 2 * j];
    float ebr = eb[c0];

    int base = (blockIdx.x * 4 + pair) * EPW;

    int sc0 = g_src[base + lane],  sc1 = g_src[base + 32 + lane];
    int dc0 = g_dst[base + lane],  dc1 = g_dst[base + 32 + lane];

    // each buffer = 2048B; this warp copies its half (1KB = 2 cp16/lane)
    uint32_t sb0 = s2u(&ea_s[pair][0][0]) + half * 1024;
    uint32_t sb1 = s2u(&ea_s[pair][1][0]) + half * 1024;
    const char* gp = (const char*)(g_ea_perm) + (size_t)base * (cDE * 4)
                   + half * 1024;
    #pragma unroll
    for (int i = 0; i < 2; i++)
        cp16(sb0 + i * 512 + lane * 16, gp + i * 512 + lane * 16);
    CP_COMMIT();
    #pragma unroll
    for (int i = 0; i < 2; i++)
        cp16(sb1 + i * 512 + lane * 16, gp + 2048 + i * 512 + lane * 16);
    CP_COMMIT();

    float acc0 = 0.f;
    int cur = __shfl_sync(0xffffffffu, dc0, 0);

    auto process = [&](const float* eabuf, int sc, int dc) {
        for (int g = 0; g < 32; g += 4) {
            int ss[4], dd[4];
            #pragma unroll
            for (int r = 0; r < 4; r++) {
                ss[r] = __shfl_sync(0xffffffffu, sc, g + r);
                dd[r] = __shfl_sync(0xffffffffu, dc, g + r);
            }
            float xa[4];
            #pragma unroll
            for (int r = 0; r < 4; r++) xa[r] = g_x[(size_t)ss[r] * cH + c0];
            #pragma unroll
            for (int r = 0; r < 4; r++) {
                if (dd[r] != cur) {   // warp-uniform
                    red_add_1(&g_u[(size_t)cur * cH + c0], acc0);
                    acc0 = 0.f;
                    cur = dd[r];
                }
                const ulonglong2* eap = (const ulonglong2*)(eabuf + (g + r) * cDE);
                ulonglong2 p0 = eap[0], p1 = eap[1], p2 = eap[2], p3 = eap[3];
                ull d0 = pack2(ebr, 0.f);
                d0 = ffma2(wreg[0], p0.x, d0);
                d0 = ffma2(wreg[1], p0.y, d0);
                d0 = ffma2(wreg[2], p1.x, d0);
                d0 = ffma2(wreg[3], p1.y, d0);
                d0 = ffma2(wreg[4], p2.x, d0);
                d0 = ffma2(wreg[5], p2.y, d0);
                d0 = ffma2(wreg[6], p3.x, d0);
                d0 = ffma2(wreg[7], p3.y, d0);
                float2 pa = unpack2(d0);
                acc0 += fmaxf(xa[r] + pa.x + pa.y, 0.f);
            }
        }
    };

    CP_WAIT1();
    __syncthreads();   // partner's buf0 copies visible
    process(&ea_s[pair][0][0], sc0, dc0);
    CP_WAIT0();
    __syncthreads();   // partner's buf1 copies visible
    process(&ea_s[pair][1][0], sc1, dc1);

    red_add_1(&g_u[(size_t)cur * cH + c0], acc0);
}

// ---------------- node update: h2 = relu(relu(u W1^T + b1) W2^T + b2) ------
template <int CIN>
__global__ void __launch_bounds__(256, 2) node_kernel(
    const float* __restrict__ w1, const float* __restrict__ b1,
    const float* __restrict__ w2, const float* __restrict__ b2)
{
    constexpr int KP1 = CIN / 2;   // 16 or 32
    constexpr int US  = KP1 + 1;
    constexpr int KP2 = cH / 2;    // 32
    constexpr int HS  = KP2 + 1;   // 33
    constexpr int WS  = KP2 + 1;

    extern __shared__ __align__(16) ull dyn[];
    ull* us2 = dyn;                    // [128 * US]
    ull* ws2 = us2 + 128 * US;         // [64 * WS]
    ull* hs2 = ws2 + 64 * WS;          // [128 * HS]
    float* hsf = (float*)hs2;

    int t = threadIdx.x;
    int lane = t & 31;
    int w = t >> 5;
    int n0 = blockIdx.x * 128;

    for (int i = t; i < 128 * KP1; i += 256) {
        int n = i / KP1, j = i % KP1;
        us2[n * US + j] = (n0 + n < cN)
            ? *(const ull*)&g_u[(size_t)(n0 + n) * CIN + 2 * j] : 0ull;
    }
    for (int i = t; i < cH * KP1; i += 256) {
        int r = i / KP1, j = i % KP1;
        ws2[r * WS + j] = ((const ull*)w1)[i];
    }
    __syncthreads();

    // ---- GEMM 1 ----
    ull acc2[4][8];
    #pragma unroll
    for (int j = 0; j < 8; j++) {
        ull b = pack2(b1[w * 8 + j], 0.f);
        #pragma unroll
        for (int i = 0; i < 4; i++) acc2[i][j] = b;
    }
    for (int kp = 0; kp < KP1; kp++) {
        ull wt[8], uv[4];
        #pragma unroll
        for (int j = 0; j < 8; j++) wt[j] = ws2[(w * 8 + j) * WS + kp];
        #pragma unroll
        for (int i = 0; i < 4; i++) uv[i] = us2[(lane + 32 * i) * US + kp];
        #pragma unroll
        for (int i = 0; i < 4; i++)
            #pragma unroll
            for (int j = 0; j < 8; j++)
                acc2[i][j] = ffma2(wt[j], uv[i], acc2[i][j]);
    }
    #pragma unroll
    for (int i = 0; i < 4; i++) {
        int n = lane + 32 * i;
        #pragma unroll
        for (int j = 0; j < 8; j += 2) {
            float2 pa = unpack2(acc2[i][j]);
            float2 pb = unpack2(acc2[i][j + 1]);
            ull pk = pack2(fmaxf(pa.x + pa.y, 0.f), fmaxf(pb.x + pb.y, 0.f));
            *(ull*)&hsf[n * (2 * HS) + w * 8 + j] = pk;
        }
    }
    __syncthreads();

    for (int i = t; i < cH * KP2; i += 256) {
        int r = i / KP2, j = i % KP2;
        ws2[r * WS + j] = ((const ull*)w2)[i];
    }
    __syncthreads();

    // ---- GEMM 2 ----
    #pragma unroll
    for (int j = 0; j < 8; j++) {
        ull b = pack2(b2[w * 8 + j], 0.f);
        #pragma unroll
        for (int i = 0; i < 4; i++) acc2[i][j] = b;
    }
    for (int kp = 0; kp < KP2; kp++) {
        ull wt[8], uv[4];
        #pragma unroll
        for (int j = 0; j < 8; j++) wt[j] = ws2[(w * 8 + j) * WS + kp];
        #pragma unroll
        for (int i = 0; i < 4; i++) uv[i] = hs2[(lane + 32 * i) * HS + kp];
        #pragma unroll
        for (int i = 0; i < 4; i++)
            #pragma unroll
            for (int j = 0; j < 8; j++)
                acc2[i][j] = ffma2(wt[j], uv[i], acc2[i][j]);
    }

    float v[4][8];
    float s[8], q[8];
    #pragma unroll
    for (int j = 0; j < 8; j++) { s[j] = 0.f; q[j] = 0.f; }
    #pragma unroll
    for (int i = 0; i < 4; i++) {
        bool valid = (n0 + lane + 32 * i) < cN;
        #pragma unroll
        for (int j = 0; j < 8; j++) {
            float2 p = unpack2(acc2[i][j]);
            float vv = valid ? fmaxf(p.x + p.y, 0.f) : 0.f;
            v[i][j] = vv;
            s[j] += vv; q[j] += vv * vv;
        }
    }
    #pragma unroll
    for (int j = 0; j < 8; j++) {
        #pragma unroll
        for (int off = 16; off > 0; off >>= 1) {
            s[j] += __shfl_xor_sync(0xffffffffu, s[j], off);
            q[j] += __shfl_xor_sync(0xffffffffu, q[j], off);
        }
    }
    if (lane == 0) {
        #pragma unroll
        for (int j = 0; j < 8; j++) {
            atomicAdd(&g_sum[w * 8 + j], s[j]);
            atomicAdd(&g_sumsq[w * 8 + j], q[j]);
        }
    }

    __syncthreads();
    #pragma unroll
    for (int i = 0; i < 4; i++) {
        int n = lane + 32 * i;
        #pragma unroll
        for (int j = 0; j < 8; j += 2) {
            ull pk = pack2(v[i][j], v[i][j + 1]);
            *(ull*)&hsf[n * (2 * HS) + w * 8 + j] = pk;
        }
    }
    __syncthreads();
    for (int i = t; i < 128 * cH / 2; i += 256) {
        int n = i / KP2, j = i % KP2;
        if (n0 + n < cN)
            *(ull*)&g_h[(size_t)(n0 + n) * cH + 2 * j] = *(ull*)&hsf[n * (2 * HS) + 2 * j];
    }
}

// ---------------- BN normalize (+relu); writes g_x and (if !last) g_u ------
__global__ void __launch_bounds__(256) norm_kernel(
    const float* __restrict__ gamma, const float* __restrict__ beta,
    const int* __restrict__ batch, int last)
{
    int idx = blockIdx.x * 256 + threadIdx.x;
    if (idx >= cN * 16) return;
    int node = idx >> 4;
    int c0 = (idx & 15) * 4;
    float4 h = ((const float4*)g_h)[idx];
    float v[4] = {h.x, h.y, h.z, h.w};
    #pragma unroll
    for (int j = 0; j < 4; j++) {
        int c = c0 + j;
        float mu  = g_sum[c]   * (1.f / cN);
        float var = g_sumsq[c] * (1.f / cN) - mu * mu;
        float sc  = rsqrtf(var + 1e-5f) * gamma[c];
        v[j] = fmaxf((v[j] - mu) * sc + beta[c], 0.f);
    }
    float4 vv = make_float4(v[0], v[1], v[2], v[3]);
    ((float4*)g_x)[idx] = vv;
    if (!last) {
        ((float4*)g_u)[idx] = vv;     // seed u = x for next layer's gather
    } else {
        int b = batch[node];
        red_add_v4(&g_pool[b * cH + c0], v[0], v[1], v[2], v[3]);
        if (c0 == 0) atomicAdd(&g_cnt[b], 1);
    }
}

// ---------------- pooled mean + MLP head -----------------------------------
__global__ void __launch_bounds__(128) head_kernel(
    const float* __restrict__ hw1, const float* __restrict__ hb1,
    const float* __restrict__ hw2, const float* __restrict__ hb2,
    float* __restrict__ out)
{
    __shared__ float p[cH], z[cMH];
    int g = blockIdx.x, t = threadIdx.x;
    if (t < cH) p[t] = g_pool[g * cH + t] / fmaxf((float)g_cnt[g], 1.f);
    __syncthreads();
    float acc = hb1[t];
    for (int c = 0; c < cH; c++) acc += p[c] * hw1[t * cH + c];
    z[t] = fmaxf(acc, 0.f);
    __syncthreads();
    if (t < cOUT) {
        float a = hb2[t];
        for (int m = 0; m < cMH; m++) a += z[m] * hw2[t * cMH + m];
        out[g * cOUT + t] = a;
    }
}

// ---------------- launch ----------------------------------------------------
extern "C" void kernel_launch(void* const* d_in, const int* in_sizes, int n_in,
                              void* d_out, int out_size)
{
    const float* x    = (const float*)d_in[0];
    const int*   ei   = (const int*)  d_in[1];
    const float* ea   = (const float*)d_in[2];
    const int*   batch= (const int*)  d_in[3];
    const float* l0ew = (const float*)d_in[4];
    const float* l0eb = (const float*)d_in[5];
    const float* l0w1 = (const float*)d_in[6];
    const float* l0b1 = (const float*)d_in[7];
    const float* l0w2 = (const float*)d_in[8];
    const float* l0b2 = (const float*)d_in[9];
    const float* ewA  = (const float*)d_in[10];  // [3, H, DE]
    const float* ebA  = (const float*)d_in[11];  // [3, H]
    const float* w1A  = (const float*)d_in[12];  // [3, H, H]
    const float* b1A  = (const float*)d_in[13];
    const float* w2A  = (const float*)d_in[14];
    const float* b2A  = (const float*)d_in[15];
    const float* bng  = (const float*)d_in[16];  // [4, H]
    const float* bnb  = (const float*)d_in[17];
    const float* hw1  = (const float*)d_in[18];
    const float* hb1  = (const float*)d_in[19];
    const float* hw2  = (const float*)d_in[20];
    const float* hb2  = (const float*)d_in[21];
    float* out = (float*)d_out;

    const int EB  = (cE + 255) / 256;      // 6250
    const int GB0 = cE / (8 * EPW);        // 3125 (warp per 64 edges)
    const int GB6 = cE / (4 * EPW);        // 6250 (warp-pair per 64 edges)
    const int NB  = (cN + 127) / 128;      // 782
    const int MB  = cN * 16 / 256;         // 6250

    const int SM32 = (128 * (cDIN / 2 + 1) + cH * 33 + 128 * 33) * 8;
    const int SM64 = (128 * (cH   / 2 + 1) + cH * 33 + 128 * 33) * 8;
    cudaFuncSetAttribute(node_kernel<cDIN>,
                         cudaFuncAttributeMaxDynamicSharedMemorySize, SM32);
    cudaFuncSetAttribute(node_kernel<cH>,
                         cudaFuncAttributeMaxDynamicSharedMemorySize, SM64);

    // CSR build (by dst) + edge_attr permutation + g_u seed
    hist_kernel<<<EB, 256>>>(ei, x);
    scan_kernel<<<1, 1024>>>();
    scatter_kernel<<<EB, 256>>>(ei, ea);

    // layer 0 (CIN = 32)
    gather0_kernel<<<GB0, 256>>>(x, l0ew, l0eb);
    node_kernel<cDIN><<<NB, 256, SM32>>>(l0w1, l0b1, l0w2, l0b2);
    norm_kernel<<<MB, 256>>>(bng, bnb, batch, 0);

    // layers 1..3 (CIN = 64): pair-split gather
    for (int i = 0; i < 3; i++) {
        int last = (i == 2) ? 1 : 0;
        gather64_kernel<<<GB6, 256>>>(ewA + (size_t)i * cH * cDE,
                                      ebA + (size_t)i * cH);
        node_kernel<cH><<<NB, 256, SM64>>>(w1A + (size_t)i * cH * cH, b1A + (size_t)i * cH,
                                           w2A + (size_t)i * cH * cH, b2A + (size_t)i * cH);
        norm_kernel<<<MB, 256>>>(bng + (size_t)(i + 1) * cH,
                                 bnb + (size_t)(i + 1) * cH, batch, last);
    }

    head_kernel<<<cG, 128>>>(hw1, hb1, hw2, hb2, out);
}